// round 3
// baseline (speedup 1.0000x reference)
#include <cuda_runtime.h>
#include <cuda_bf16.h>
#include <math.h>

// Problem constants (fixed by the dataset)
#define NN 100000
#define EE 1600000
#define FF 128
#define DIM 128
#define DIM2 64
#define DIM4 32
#define CC 6

// ---------------- device scratch (allocation-free rule, 16B aligned) ----------------
__device__ float  g_deg [NN];
__device__ float  g_dinv[NN];
__device__ float4 g_hw4 [(size_t)NN * DIM  / 4];
__device__ float4 g_agg4[(size_t)NN * DIM  / 4];
__device__ float4 g_h4  [(size_t)NN * DIM  / 4];
__device__ float4 g_h24 [(size_t)NN * DIM2 / 4];
__device__ float4 g_h34 [(size_t)NN * DIM4 / 4];

// ---------------- degree / dinv ----------------
__global__ void zero_deg_k() {
    int i = blockIdx.x * blockDim.x + threadIdx.x;
    if (i < NN) g_deg[i] = 0.f;
}

__global__ void deg_k(const int* __restrict__ dst) {
    int e = blockIdx.x * blockDim.x + threadIdx.x;
    if (e < EE) atomicAdd(&g_deg[dst[e]], 1.0f);
}

__global__ void dinv_k() {
    int i = blockIdx.x * blockDim.x + threadIdx.x;
    if (i < NN) g_dinv[i] = rsqrtf(g_deg[i] + 1.0f);
}

// ---------------- register-tiled fp32 GEMM ----------------
// C[M x BN] = A[M x K] @ W[K x BN]
// EPI == 0 : g_hw = hw,  g_agg = hw * dinv[row]^2   (conv path; bias/tanh later)
// EPI == 1 : out = tanh(acc + bias[col])            (fc path)
// SRC: 0 = Aparam (x), 1 = g_h, 2 = g_h2
// OUT: (EPI==1 only) 1 = g_h2, 2 = g_h3
template<int K, int BN, int TM, int TN, int EPI, int SRC, int OUT>
__global__ void gemm_k(const float* __restrict__ Aparam, const float* __restrict__ W,
                       const float* __restrict__ bias, int M)
{
    constexpr int BM = 64;
    constexpr int KT = 32;
    constexpr int NT = (BM / TM) * (BN / TN);
    __shared__ float As[BM][KT + 1];
    __shared__ float Ws[KT][BN + 1];

    const float* A = (SRC == 0) ? Aparam
                   : (SRC == 1) ? (const float*)g_h4
                                : (const float*)g_h24;
    float* O1 = (EPI == 0) ? (float*)g_hw4
              : (OUT == 1) ? (float*)g_h24
                           : (float*)g_h34;
    float* O2 = (float*)g_agg4;

    const int tx  = threadIdx.x;                // 0 .. BN/TN-1
    const int ty  = threadIdx.y;                // 0 .. BM/TM-1
    const int tid = ty * (BN / TN) + tx;
    const int row0 = blockIdx.x * BM;

    float acc[TM][TN];
#pragma unroll
    for (int i = 0; i < TM; ++i)
#pragma unroll
        for (int j = 0; j < TN; ++j) acc[i][j] = 0.f;

    for (int kt = 0; kt < K; kt += KT) {
        for (int i = tid; i < BM * KT; i += NT) {
            int r = i / KT, c = i % KT;
            int gr = row0 + r;
            As[r][c] = (gr < M) ? A[(size_t)gr * K + kt + c] : 0.f;
        }
        for (int i = tid; i < KT * BN; i += NT) {
            int r = i / BN, c = i % BN;
            Ws[r][c] = W[(size_t)(kt + r) * BN + c];
        }
        __syncthreads();

#pragma unroll
        for (int k = 0; k < KT; ++k) {
            float a[TM], w[TN];
#pragma unroll
            for (int i = 0; i < TM; ++i) a[i] = As[ty * TM + i][k];
#pragma unroll
            for (int j = 0; j < TN; ++j) w[j] = Ws[k][tx + j * (BN / TN)];
#pragma unroll
            for (int i = 0; i < TM; ++i)
#pragma unroll
                for (int j = 0; j < TN; ++j) acc[i][j] = fmaf(a[i], w[j], acc[i][j]);
        }
        __syncthreads();
    }

#pragma unroll
    for (int i = 0; i < TM; ++i) {
        int row = row0 + ty * TM + i;
        if (row >= M) continue;
        float dd = 0.f;
        if (EPI == 0) { float d = g_dinv[row]; dd = d * d; }
#pragma unroll
        for (int j = 0; j < TN; ++j) {
            int col = tx + j * (BN / TN);
            float v = acc[i][j];
            if (EPI == 0) {
                O1[(size_t)row * BN + col] = v;
                O2[(size_t)row * BN + col] = v * dd;
            } else {
                O1[(size_t)row * BN + col] = tanhf(v + bias[col]);
            }
        }
    }
}

// ---------------- edge scatter: agg[dst] += dinv[src]*dinv[dst] * hw[src] ----------------
// one warp per edge, lane handles one float4 (128 floats total)
__global__ void scatter_k(const int* __restrict__ src, const int* __restrict__ dst)
{
    int warp = (blockIdx.x * blockDim.x + threadIdx.x) >> 5;
    int lane = threadIdx.x & 31;
    if (warp >= EE) return;
    int s = src[warp];
    int d = dst[warp];
    float coef = g_dinv[s] * g_dinv[d];
    float4 v = g_hw4[(size_t)s * (DIM / 4) + lane];
    v.x *= coef; v.y *= coef; v.z *= coef; v.w *= coef;
#if __CUDA_ARCH__ >= 900
    atomicAdd(&g_agg4[(size_t)d * (DIM / 4) + lane], v);
#else
    float* ap = (float*)&g_agg4[(size_t)d * (DIM / 4) + lane];
    atomicAdd(ap + 0, v.x);
    atomicAdd(ap + 1, v.y);
    atomicAdd(ap + 2, v.z);
    atomicAdd(ap + 3, v.w);
#endif
}

// ---------------- activation: h = tanh(agg + b) ----------------
__global__ void act_k(const float* __restrict__ bias)
{
    size_t i = (size_t)blockIdx.x * blockDim.x + threadIdx.x;
    if (i < (size_t)NN * DIM) {
        const float* agg = (const float*)g_agg4;
        float* h = (float*)g_h4;
        h[i] = tanhf(agg[i] + bias[i & (DIM - 1)]);
    }
}

// ---------------- final per-edge classifier + e output ----------------
// warp per edge: lane l carries h3[src][l] and h3[dst][l]
__global__ void edge_out_k(const int* __restrict__ src, const int* __restrict__ dst,
                           const float* __restrict__ Wcls, const float* __restrict__ bcls,
                           float* __restrict__ out, float* __restrict__ e_out)
{
    int warp = (blockIdx.x * blockDim.x + threadIdx.x) >> 5;
    int lane = threadIdx.x & 31;
    if (warp >= EE) return;
    int s = src[warp];
    int d = dst[warp];
    const float* h3 = (const float*)g_h34;
    float a = h3[(size_t)s * DIM4 + lane];
    float b = h3[(size_t)d * DIM4 + lane];
    e_out[(size_t)warp * 64 + lane]      = a;
    e_out[(size_t)warp * 64 + 32 + lane] = b;

    float r[CC];
#pragma unroll
    for (int c = 0; c < CC; ++c) {
        float p = a * Wcls[lane * CC + c] + b * Wcls[(32 + lane) * CC + c];
#pragma unroll
        for (int o = 16; o; o >>= 1) p += __shfl_xor_sync(0xFFFFFFFFu, p, o);
        r[c] = p;
    }
    if (lane == 0) {
#pragma unroll
        for (int c = 0; c < CC; ++c)
            out[(size_t)warp * CC + c] = r[c] + bcls[c];
    }
}

// ---------------- launch ----------------
extern "C" void kernel_launch(void* const* d_in, const int* in_sizes, int n_in,
                              void* d_out, int out_size)
{
    const float* x    = (const float*)d_in[0];
    const int*   ei   = (const int*)d_in[1];     // int32! (JAX x64 disabled)
    // d_in[2] = batch (unused)
    const float* W1   = (const float*)d_in[3];
    const float* b1   = (const float*)d_in[4];
    const float* Wc   = (const float*)d_in[5];   // [2,128,128]
    const float* bc   = (const float*)d_in[6];   // [2,128]
    const float* W2   = (const float*)d_in[7];
    const float* b2   = (const float*)d_in[8];
    const float* W3   = (const float*)d_in[9];
    const float* b3   = (const float*)d_in[10];
    const float* Wcls = (const float*)d_in[11];
    const float* bcls = (const float*)d_in[12];

    const int* src = ei;
    const int* dst = ei + EE;

    float* out_logits = (float*)d_out;                       // [E, 6]
    float* out_e      = (float*)d_out + (size_t)EE * CC;     // [E, 64]

    // degree -> dinv
    zero_deg_k<<<(NN + 255) / 256, 256>>>();
    deg_k<<<(EE + 255) / 256, 256>>>(dst);
    dinv_k<<<(NN + 255) / 256, 256>>>();

    const int gemm_blocks = (NN + 63) / 64;
    const int scat_blocks = (int)(((long long)EE * 32 + 255) / 256);
    const int act_blocks  = (int)(((size_t)NN * DIM + 255) / 256);

    // ---- conv layer 1 (reads x) ----
    gemm_k<128, 128, 4, 8, 0, 0, 0><<<gemm_blocks, dim3(16, 16)>>>(x, W1, nullptr, NN);
    scatter_k<<<scat_blocks, 256>>>(src, dst);
    act_k<<<act_blocks, 256>>>(b1);

    // ---- conv layers 2,3 (read g_h) ----
    for (int layer = 0; layer < 2; ++layer) {
        const float* W = Wc + (size_t)layer * DIM * DIM;
        const float* b = bc + (size_t)layer * DIM;
        gemm_k<128, 128, 4, 8, 0, 1, 0><<<gemm_blocks, dim3(16, 16)>>>(nullptr, W, nullptr, NN);
        scatter_k<<<scat_blocks, 256>>>(src, dst);
        act_k<<<act_blocks, 256>>>(b);
    }

    // ---- fc layers ----
    gemm_k<128, 64, 4, 4, 1, 1, 1><<<gemm_blocks, dim3(16, 16)>>>(nullptr, W2, b2, NN);
    gemm_k< 64, 32, 4, 4, 1, 2, 2><<<gemm_blocks, dim3( 8, 16)>>>(nullptr, W3, b3, NN);

    // ---- edge classifier + e ----
    edge_out_k<<<scat_blocks, 256>>>(src, dst, Wcls, bcls, out_logits, out_e);
}

// round 4
// speedup vs baseline: 1.4754x; 1.4754x over previous
#include <cuda_runtime.h>
#include <cuda_bf16.h>
#include <math.h>

// Problem constants (fixed by the dataset)
#define NN 100000
#define EE 1600000
#define FF 128
#define DIM 128
#define DIM2 64
#define DIM4 32
#define CC 6

#define SCAN_BLK 1024
#define NBLK ((NN + SCAN_BLK - 1) / SCAN_BLK)   // 98

// ---------------- device scratch (allocation-free rule, 16B aligned) ----------------
__device__ float  g_dinv[NN];
__device__ int    g_cnt [NN];
__device__ int    g_rp  [NN];
__device__ int    g_fill[NN];
__device__ int    g_bsum[NBLK];
__device__ int    g_boff[NBLK];
__device__ int    g_eidx[EE];
__device__ float4 g_hw4 [(size_t)NN * DIM  / 4];
__device__ float4 g_h4  [(size_t)NN * DIM  / 4];
__device__ float4 g_h24 [(size_t)NN * DIM2 / 4];
__device__ float4 g_h34 [(size_t)NN * DIM4 / 4];

// ---------------- CSR build ----------------
__global__ void zero_cnt_k() {
    int i = blockIdx.x * blockDim.x + threadIdx.x;
    if (i < NN) g_cnt[i] = 0;
}

__global__ void count_k(const int* __restrict__ dst) {
    int e = blockIdx.x * blockDim.x + threadIdx.x;
    if (e < EE) atomicAdd(&g_cnt[dst[e]], 1);
}

// per-block exclusive scan (Hillis-Steele in smem) + block totals
__global__ void scanA_k() {
    __shared__ int sh[SCAN_BLK];
    int t = threadIdx.x, b = blockIdx.x;
    int i = b * SCAN_BLK + t;
    int v = (i < NN) ? g_cnt[i] : 0;
    sh[t] = v;
    __syncthreads();
    for (int off = 1; off < SCAN_BLK; off <<= 1) {
        int add = (t >= off) ? sh[t - off] : 0;
        __syncthreads();
        sh[t] += add;
        __syncthreads();
    }
    if (i < NN) g_rp[i] = sh[t] - v;      // exclusive within block
    if (t == SCAN_BLK - 1) g_bsum[b] = sh[t];
}

__global__ void scanB_k() {
    if (threadIdx.x == 0 && blockIdx.x == 0) {
        int run = 0;
        for (int b = 0; b < NBLK; ++b) { g_boff[b] = run; run += g_bsum[b]; }
    }
}

// finalize row_ptr, init fill cursors, compute dinv from degree
__global__ void scanC_k() {
    int i = blockIdx.x * blockDim.x + threadIdx.x;
    if (i < NN) {
        int rp = g_rp[i] + g_boff[i / SCAN_BLK];
        g_rp[i]   = rp;
        g_fill[i] = rp;
        g_dinv[i] = rsqrtf((float)g_cnt[i] + 1.0f);
    }
}

__global__ void fill_k(const int* __restrict__ src, const int* __restrict__ dst) {
    int e = blockIdx.x * blockDim.x + threadIdx.x;
    if (e < EE) {
        int pos = atomicAdd(&g_fill[dst[e]], 1);
        g_eidx[pos] = src[e];
    }
}

// ---------------- register-tiled fp32 GEMM ----------------
// C[M x BN] = A[M x K] @ W[K x BN]
// EPI == 0 : g_hw = acc                      (conv path; agg/bias/tanh in gather)
// EPI == 1 : out  = tanh(acc + bias[col])    (fc path)
// SRC: 0 = Aparam (x), 1 = g_h, 2 = g_h2
// OUT: (EPI==1 only) 1 = g_h2, 2 = g_h3
template<int K, int BN, int TM, int TN, int EPI, int SRC, int OUT>
__global__ void gemm_k(const float* __restrict__ Aparam, const float* __restrict__ W,
                       const float* __restrict__ bias, int M)
{
    constexpr int BM = 64;
    constexpr int KT = 32;
    constexpr int NT = (BM / TM) * (BN / TN);
    __shared__ float As[BM][KT + 1];
    __shared__ float Ws[KT][BN + 1];

    const float* A = (SRC == 0) ? Aparam
                   : (SRC == 1) ? (const float*)g_h4
                                : (const float*)g_h24;
    float* O1 = (EPI == 0) ? (float*)g_hw4
              : (OUT == 1) ? (float*)g_h24
                           : (float*)g_h34;

    const int tx  = threadIdx.x;                // 0 .. BN/TN-1
    const int ty  = threadIdx.y;                // 0 .. BM/TM-1
    const int tid = ty * (BN / TN) + tx;
    const int row0 = blockIdx.x * BM;

    float acc[TM][TN];
#pragma unroll
    for (int i = 0; i < TM; ++i)
#pragma unroll
        for (int j = 0; j < TN; ++j) acc[i][j] = 0.f;

    for (int kt = 0; kt < K; kt += KT) {
        for (int i = tid; i < BM * KT; i += NT) {
            int r = i / KT, c = i % KT;
            int gr = row0 + r;
            As[r][c] = (gr < M) ? A[(size_t)gr * K + kt + c] : 0.f;
        }
        for (int i = tid; i < KT * BN; i += NT) {
            int r = i / BN, c = i % BN;
            Ws[r][c] = W[(size_t)(kt + r) * BN + c];
        }
        __syncthreads();

#pragma unroll
        for (int k = 0; k < KT; ++k) {
            float a[TM], w[TN];
#pragma unroll
            for (int i = 0; i < TM; ++i) a[i] = As[ty * TM + i][k];
#pragma unroll
            for (int j = 0; j < TN; ++j) w[j] = Ws[k][tx + j * (BN / TN)];
#pragma unroll
            for (int i = 0; i < TM; ++i)
#pragma unroll
                for (int j = 0; j < TN; ++j) acc[i][j] = fmaf(a[i], w[j], acc[i][j]);
        }
        __syncthreads();
    }

#pragma unroll
    for (int i = 0; i < TM; ++i) {
        int row = row0 + ty * TM + i;
        if (row >= M) continue;
#pragma unroll
        for (int j = 0; j < TN; ++j) {
            int col = tx + j * (BN / TN);
            float v = acc[i][j];
            if (EPI == 0) O1[(size_t)row * BN + col] = v;
            else          O1[(size_t)row * BN + col] = tanhf(v + bias[col]);
        }
    }
}

// ---------------- CSR gather + self-loop + bias + tanh (replaces scatter+act) ----------------
// warp per dst node, lane holds one float4 (128 features total)
__global__ void gather_k(const float* __restrict__ bias)
{
    int d    = (blockIdx.x * blockDim.x + threadIdx.x) >> 5;
    int lane = threadIdx.x & 31;
    if (d >= NN) return;

    int   beg = g_rp[d];
    int   cnt = g_cnt[d];
    float di  = g_dinv[d];

    float4 self = g_hw4[(size_t)d * (DIM / 4) + lane];
    float  dd   = di * di;
    float4 acc  = make_float4(self.x * dd, self.y * dd, self.z * dd, self.w * dd);

    int j = 0;
    for (; j + 1 < cnt; j += 2) {
        int s0 = g_eidx[beg + j];
        int s1 = g_eidx[beg + j + 1];
        float  c0 = g_dinv[s0] * di;
        float  c1 = g_dinv[s1] * di;
        float4 v0 = g_hw4[(size_t)s0 * (DIM / 4) + lane];
        float4 v1 = g_hw4[(size_t)s1 * (DIM / 4) + lane];
        acc.x = fmaf(c0, v0.x, acc.x); acc.y = fmaf(c0, v0.y, acc.y);
        acc.z = fmaf(c0, v0.z, acc.z); acc.w = fmaf(c0, v0.w, acc.w);
        acc.x = fmaf(c1, v1.x, acc.x); acc.y = fmaf(c1, v1.y, acc.y);
        acc.z = fmaf(c1, v1.z, acc.z); acc.w = fmaf(c1, v1.w, acc.w);
    }
    if (j < cnt) {
        int s0 = g_eidx[beg + j];
        float  c0 = g_dinv[s0] * di;
        float4 v0 = g_hw4[(size_t)s0 * (DIM / 4) + lane];
        acc.x = fmaf(c0, v0.x, acc.x); acc.y = fmaf(c0, v0.y, acc.y);
        acc.z = fmaf(c0, v0.z, acc.z); acc.w = fmaf(c0, v0.w, acc.w);
    }

    float4 b4 = reinterpret_cast<const float4*>(bias)[lane];
    g_h4[(size_t)d * (DIM / 4) + lane] =
        make_float4(tanhf(acc.x + b4.x), tanhf(acc.y + b4.y),
                    tanhf(acc.z + b4.z), tanhf(acc.w + b4.w));
}

// ---------------- final per-edge classifier + e output ----------------
// warp per edge: lane l carries h3[src][l] and h3[dst][l]
__global__ void edge_out_k(const int* __restrict__ src, const int* __restrict__ dst,
                           const float* __restrict__ Wcls, const float* __restrict__ bcls,
                           float* __restrict__ out, float* __restrict__ e_out)
{
    int warp = (blockIdx.x * blockDim.x + threadIdx.x) >> 5;
    int lane = threadIdx.x & 31;
    if (warp >= EE) return;
    int s = src[warp];
    int d = dst[warp];
    const float* h3 = (const float*)g_h34;
    float a = h3[(size_t)s * DIM4 + lane];
    float b = h3[(size_t)d * DIM4 + lane];
    e_out[(size_t)warp * 64 + lane]      = a;
    e_out[(size_t)warp * 64 + 32 + lane] = b;

    float r[CC];
#pragma unroll
    for (int c = 0; c < CC; ++c) {
        float p = a * Wcls[lane * CC + c] + b * Wcls[(32 + lane) * CC + c];
#pragma unroll
        for (int o = 16; o; o >>= 1) p += __shfl_xor_sync(0xFFFFFFFFu, p, o);
        r[c] = p;
    }
    if (lane == 0) {
#pragma unroll
        for (int c = 0; c < CC; ++c)
            out[(size_t)warp * CC + c] = r[c] + bcls[c];
    }
}

// ---------------- launch ----------------
extern "C" void kernel_launch(void* const* d_in, const int* in_sizes, int n_in,
                              void* d_out, int out_size)
{
    const float* x    = (const float*)d_in[0];
    const int*   ei   = (const int*)d_in[1];     // int32 (JAX x64 disabled)
    // d_in[2] = batch (unused)
    const float* W1   = (const float*)d_in[3];
    const float* b1   = (const float*)d_in[4];
    const float* Wc   = (const float*)d_in[5];   // [2,128,128]
    const float* bc   = (const float*)d_in[6];   // [2,128]
    const float* W2   = (const float*)d_in[7];
    const float* b2   = (const float*)d_in[8];
    const float* W3   = (const float*)d_in[9];
    const float* b3   = (const float*)d_in[10];
    const float* Wcls = (const float*)d_in[11];
    const float* bcls = (const float*)d_in[12];

    const int* src = ei;
    const int* dst = ei + EE;

    float* out_logits = (float*)d_out;                       // [E, 6]
    float* out_e      = (float*)d_out + (size_t)EE * CC;     // [E, 64]

    const int node_blocks = (NN + 255) / 256;
    const int edge_blocks = (EE + 255) / 256;
    const int gemm_blocks = (NN + 63) / 64;
    const int warp_blocks = (int)(((long long)EE * 32 + 255) / 256);   // warp-per-edge
    const int gath_blocks = (int)(((long long)NN * 32 + 255) / 256);   // warp-per-node

    // ---- CSR build (also produces dinv) ----
    zero_cnt_k<<<node_blocks, 256>>>();
    count_k<<<edge_blocks, 256>>>(dst);
    scanA_k<<<NBLK, SCAN_BLK>>>();
    scanB_k<<<1, 32>>>();
    scanC_k<<<node_blocks, 256>>>();
    fill_k<<<edge_blocks, 256>>>(src, dst);

    // ---- conv layer 1 (reads x) ----
    gemm_k<128, 128, 4, 8, 0, 0, 0><<<gemm_blocks, dim3(16, 16)>>>(x, W1, nullptr, NN);
    gather_k<<<gath_blocks, 256>>>(b1);

    // ---- conv layers 2,3 (read g_h) ----
    for (int layer = 0; layer < 2; ++layer) {
        const float* W = Wc + (size_t)layer * DIM * DIM;
        const float* b = bc + (size_t)layer * DIM;
        gemm_k<128, 128, 4, 8, 0, 1, 0><<<gemm_blocks, dim3(16, 16)>>>(nullptr, W, nullptr, NN);
        gather_k<<<gath_blocks, 256>>>(b);
    }

    // ---- fc layers ----
    gemm_k<128, 64, 4, 4, 1, 1, 1><<<gemm_blocks, dim3(16, 16)>>>(nullptr, W2, b2, NN);
    gemm_k< 64, 32, 4, 4, 1, 2, 2><<<gemm_blocks, dim3( 8, 16)>>>(nullptr, W3, b3, NN);

    // ---- edge classifier + e ----
    edge_out_k<<<warp_blocks, 256>>>(src, dst, Wcls, bcls, out_logits, out_e);
}

// round 5
// speedup vs baseline: 1.5201x; 1.0303x over previous
#include <cuda_runtime.h>
#include <cuda_bf16.h>
#include <math.h>

// Problem constants (fixed by the dataset)
#define NN 100000
#define EE 1600000
#define FF 128
#define DIM 128
#define DIM2 64
#define DIM4 32
#define CC 6

#define SCAN_BLK 1024
#define NBLK ((NN + SCAN_BLK - 1) / SCAN_BLK)   // 98

// ---------------- device scratch (allocation-free rule, 16B aligned) ----------------
__device__ float  g_dinv[NN];
__device__ int    g_cnt [NN];
__device__ int    g_rp  [NN];
__device__ int    g_fill[NN];
__device__ int    g_bsum[NBLK];
__device__ int    g_boff[NBLK];
__device__ int    g_eidx[EE];
__device__ float4 g_hw4 [(size_t)NN * DIM  / 4];
__device__ float4 g_h4  [(size_t)NN * DIM  / 4];
__device__ float4 g_h24 [(size_t)NN * DIM2 / 4];
__device__ float4 g_h34 [(size_t)NN * DIM4 / 4];

// ---------------- CSR build ----------------
__global__ void zero_cnt_k() {
    int i = blockIdx.x * blockDim.x + threadIdx.x;
    if (i < NN) g_cnt[i] = 0;
}

__global__ void count_k(const int* __restrict__ dst) {
    int e = blockIdx.x * blockDim.x + threadIdx.x;
    if (e < EE) atomicAdd(&g_cnt[dst[e]], 1);
}

// per-block exclusive scan (Hillis-Steele in smem) + block totals
__global__ void scanA_k() {
    __shared__ int sh[SCAN_BLK];
    int t = threadIdx.x, b = blockIdx.x;
    int i = b * SCAN_BLK + t;
    int v = (i < NN) ? g_cnt[i] : 0;
    sh[t] = v;
    __syncthreads();
    for (int off = 1; off < SCAN_BLK; off <<= 1) {
        int add = (t >= off) ? sh[t - off] : 0;
        __syncthreads();
        sh[t] += add;
        __syncthreads();
    }
    if (i < NN) g_rp[i] = sh[t] - v;      // exclusive within block
    if (t == SCAN_BLK - 1) g_bsum[b] = sh[t];
}

__global__ void scanB_k() {
    if (threadIdx.x == 0 && blockIdx.x == 0) {
        int run = 0;
        for (int b = 0; b < NBLK; ++b) { g_boff[b] = run; run += g_bsum[b]; }
    }
}

// finalize row_ptr, init fill cursors, compute dinv from degree
__global__ void scanC_k() {
    int i = blockIdx.x * blockDim.x + threadIdx.x;
    if (i < NN) {
        int rp = g_rp[i] + g_boff[i / SCAN_BLK];
        g_rp[i]   = rp;
        g_fill[i] = rp;
        g_dinv[i] = rsqrtf((float)g_cnt[i] + 1.0f);
    }
}

__global__ void fill_k(const int* __restrict__ src, const int* __restrict__ dst) {
    int e = blockIdx.x * blockDim.x + threadIdx.x;
    if (e < EE) {
        int pos = atomicAdd(&g_fill[dst[e]], 1);
        g_eidx[pos] = src[e];
    }
}

// ---------------- big-tile fp32 conv GEMM: hw[M x 128] = A[M x 128] @ W[128 x 128] ----------------
// BM=128, BN=128, KT=16, 256 threads, 8x8 microtile
// SRC: 0 = Aparam (x), 1 = g_h
template<int SRC>
__global__ void __launch_bounds__(256, 2) cgemm_k(const float* __restrict__ Aparam,
                                                  const float* __restrict__ W, int M)
{
    __shared__ float As[128][20];    // row stride 20 (pad, float4-aligned)
    __shared__ float Ws[16][132];    // row stride 132 (pad, float4-aligned)

    const float* A = (SRC == 0) ? Aparam : (const float*)g_h4;
    float* O = (float*)g_hw4;

    const int tid = threadIdx.x;
    const int tx = tid & 15;         // 0..15  -> col block of 8
    const int ty = tid >> 4;         // 0..15  -> row block of 8
    const int row0 = blockIdx.x * 128;

    float acc[8][8];
#pragma unroll
    for (int i = 0; i < 8; ++i)
#pragma unroll
        for (int j = 0; j < 8; ++j) acc[i][j] = 0.f;

    for (int kt = 0; kt < 128; kt += 16) {
        // A tile: 128 rows x 16 cols = 512 float4, 2 per thread
#pragma unroll
        for (int u = 0; u < 2; ++u) {
            int f = tid + u * 256;
            int r = f >> 2, c = (f & 3) << 2;
            int gr = row0 + r;
            float4 v = make_float4(0.f, 0.f, 0.f, 0.f);
            if (gr < M) v = __ldg((const float4*)(A + (size_t)gr * 128 + kt + c));
            *(float4*)&As[r][c] = v;
        }
        // W tile: 16 rows x 128 cols = 512 float4, 2 per thread
#pragma unroll
        for (int u = 0; u < 2; ++u) {
            int f = tid + u * 256;
            int r = f >> 5, c = (f & 31) << 2;
            *(float4*)&Ws[r][c] = __ldg((const float4*)(W + (size_t)(kt + r) * 128 + c));
        }
        __syncthreads();

#pragma unroll
        for (int k = 0; k < 16; ++k) {
            float4 w0 = *(const float4*)&Ws[k][tx * 8];
            float4 w1 = *(const float4*)&Ws[k][tx * 8 + 4];
            float w[8] = {w0.x, w0.y, w0.z, w0.w, w1.x, w1.y, w1.z, w1.w};
            float a[8];
#pragma unroll
            for (int i = 0; i < 8; ++i) a[i] = As[ty * 8 + i][k];
#pragma unroll
            for (int i = 0; i < 8; ++i)
#pragma unroll
                for (int j = 0; j < 8; ++j) acc[i][j] = fmaf(a[i], w[j], acc[i][j]);
        }
        __syncthreads();
    }

#pragma unroll
    for (int i = 0; i < 8; ++i) {
        int row = row0 + ty * 8 + i;
        if (row >= M) continue;
        float4 o0 = make_float4(acc[i][0], acc[i][1], acc[i][2], acc[i][3]);
        float4 o1 = make_float4(acc[i][4], acc[i][5], acc[i][6], acc[i][7]);
        float4* op = (float4*)(O + (size_t)row * 128 + tx * 8);
        op[0] = o0;
        op[1] = o1;
    }
}

// ---------------- small fp32 GEMM for fc layers: out = tanh(A@W + b) ----------------
// SRC: 1 = g_h, 2 = g_h2 ; OUT: 1 = g_h2, 2 = g_h3
template<int K, int BN, int TM, int TN, int SRC, int OUT>
__global__ void gemm_k(const float* __restrict__ W, const float* __restrict__ bias, int M)
{
    constexpr int BM = 64;
    constexpr int KT = 32;
    constexpr int NT = (BM / TM) * (BN / TN);
    __shared__ float As[BM][KT + 1];
    __shared__ float Ws[KT][BN + 1];

    const float* A = (SRC == 1) ? (const float*)g_h4 : (const float*)g_h24;
    float* O1 = (OUT == 1) ? (float*)g_h24 : (float*)g_h34;

    const int tx  = threadIdx.x;
    const int ty  = threadIdx.y;
    const int tid = ty * (BN / TN) + tx;
    const int row0 = blockIdx.x * BM;

    float acc[TM][TN];
#pragma unroll
    for (int i = 0; i < TM; ++i)
#pragma unroll
        for (int j = 0; j < TN; ++j) acc[i][j] = 0.f;

    for (int kt = 0; kt < K; kt += KT) {
        for (int i = tid; i < BM * KT; i += NT) {
            int r = i / KT, c = i % KT;
            int gr = row0 + r;
            As[r][c] = (gr < M) ? A[(size_t)gr * K + kt + c] : 0.f;
        }
        for (int i = tid; i < KT * BN; i += NT) {
            int r = i / BN, c = i % BN;
            Ws[r][c] = W[(size_t)(kt + r) * BN + c];
        }
        __syncthreads();

#pragma unroll
        for (int k = 0; k < KT; ++k) {
            float a[TM], w[TN];
#pragma unroll
            for (int i = 0; i < TM; ++i) a[i] = As[ty * TM + i][k];
#pragma unroll
            for (int j = 0; j < TN; ++j) w[j] = Ws[k][tx + j * (BN / TN)];
#pragma unroll
            for (int i = 0; i < TM; ++i)
#pragma unroll
                for (int j = 0; j < TN; ++j) acc[i][j] = fmaf(a[i], w[j], acc[i][j]);
        }
        __syncthreads();
    }

#pragma unroll
    for (int i = 0; i < TM; ++i) {
        int row = row0 + ty * TM + i;
        if (row >= M) continue;
#pragma unroll
        for (int j = 0; j < TN; ++j) {
            int col = tx + j * (BN / TN);
            O1[(size_t)row * BN + col] = tanhf(acc[i][j] + bias[col]);
        }
    }
}

// ---------------- CSR gather + self-loop + bias + tanh ----------------
// warp per dst node, lane holds one float4 (128 features total), 4-deep MLP
__global__ void gather_k(const float* __restrict__ bias)
{
    int d    = (blockIdx.x * blockDim.x + threadIdx.x) >> 5;
    int lane = threadIdx.x & 31;
    if (d >= NN) return;

    int   beg = __ldg(&g_rp[d]);
    int   cnt = __ldg(&g_cnt[d]);
    float di  = __ldg(&g_dinv[d]);

    float4 self = __ldg(&g_hw4[(size_t)d * (DIM / 4) + lane]);
    float  dd   = di * di;
    float4 acc  = make_float4(self.x * dd, self.y * dd, self.z * dd, self.w * dd);

    int j = 0;
    for (; j + 3 < cnt; j += 4) {
        int s0 = __ldg(&g_eidx[beg + j]);
        int s1 = __ldg(&g_eidx[beg + j + 1]);
        int s2 = __ldg(&g_eidx[beg + j + 2]);
        int s3 = __ldg(&g_eidx[beg + j + 3]);
        float c0 = __ldg(&g_dinv[s0]) * di;
        float c1 = __ldg(&g_dinv[s1]) * di;
        float c2 = __ldg(&g_dinv[s2]) * di;
        float c3 = __ldg(&g_dinv[s3]) * di;
        float4 v0 = __ldg(&g_hw4[(size_t)s0 * (DIM / 4) + lane]);
        float4 v1 = __ldg(&g_hw4[(size_t)s1 * (DIM / 4) + lane]);
        float4 v2 = __ldg(&g_hw4[(size_t)s2 * (DIM / 4) + lane]);
        float4 v3 = __ldg(&g_hw4[(size_t)s3 * (DIM / 4) + lane]);
        acc.x = fmaf(c0, v0.x, acc.x); acc.y = fmaf(c0, v0.y, acc.y);
        acc.z = fmaf(c0, v0.z, acc.z); acc.w = fmaf(c0, v0.w, acc.w);
        acc.x = fmaf(c1, v1.x, acc.x); acc.y = fmaf(c1, v1.y, acc.y);
        acc.z = fmaf(c1, v1.z, acc.z); acc.w = fmaf(c1, v1.w, acc.w);
        acc.x = fmaf(c2, v2.x, acc.x); acc.y = fmaf(c2, v2.y, acc.y);
        acc.z = fmaf(c2, v2.z, acc.z); acc.w = fmaf(c2, v2.w, acc.w);
        acc.x = fmaf(c3, v3.x, acc.x); acc.y = fmaf(c3, v3.y, acc.y);
        acc.z = fmaf(c3, v3.z, acc.z); acc.w = fmaf(c3, v3.w, acc.w);
    }
    for (; j < cnt; ++j) {
        int s0 = __ldg(&g_eidx[beg + j]);
        float  c0 = __ldg(&g_dinv[s0]) * di;
        float4 v0 = __ldg(&g_hw4[(size_t)s0 * (DIM / 4) + lane]);
        acc.x = fmaf(c0, v0.x, acc.x); acc.y = fmaf(c0, v0.y, acc.y);
        acc.z = fmaf(c0, v0.z, acc.z); acc.w = fmaf(c0, v0.w, acc.w);
    }

    float4 b4 = __ldg(&((const float4*)bias)[lane]);
    g_h4[(size_t)d * (DIM / 4) + lane] =
        make_float4(tanhf(acc.x + b4.x), tanhf(acc.y + b4.y),
                    tanhf(acc.z + b4.z), tanhf(acc.w + b4.w));
}

// ---------------- final per-edge classifier + e output ----------------
__global__ void edge_out_k(const int* __restrict__ src, const int* __restrict__ dst,
                           const float* __restrict__ Wcls, const float* __restrict__ bcls,
                           float* __restrict__ out, float* __restrict__ e_out)
{
    int warp = (blockIdx.x * blockDim.x + threadIdx.x) >> 5;
    int lane = threadIdx.x & 31;
    if (warp >= EE) return;
    int s = __ldg(&src[warp]);
    int d = __ldg(&dst[warp]);
    const float* h3 = (const float*)g_h34;
    float a = __ldg(&h3[(size_t)s * DIM4 + lane]);
    float b = __ldg(&h3[(size_t)d * DIM4 + lane]);
    e_out[(size_t)warp * 64 + lane]      = a;
    e_out[(size_t)warp * 64 + 32 + lane] = b;

    float r[CC];
#pragma unroll
    for (int c = 0; c < CC; ++c) {
        float p = a * __ldg(&Wcls[lane * CC + c]) + b * __ldg(&Wcls[(32 + lane) * CC + c]);
#pragma unroll
        for (int o = 16; o; o >>= 1) p += __shfl_xor_sync(0xFFFFFFFFu, p, o);
        r[c] = p;
    }
    if (lane == 0) {
#pragma unroll
        for (int c = 0; c < CC; ++c)
            out[(size_t)warp * CC + c] = r[c] + bcls[c];
    }
}

// ---------------- launch ----------------
extern "C" void kernel_launch(void* const* d_in, const int* in_sizes, int n_in,
                              void* d_out, int out_size)
{
    const float* x    = (const float*)d_in[0];
    const int*   ei   = (const int*)d_in[1];     // int32 (JAX x64 disabled)
    // d_in[2] = batch (unused)
    const float* W1   = (const float*)d_in[3];
    const float* b1   = (const float*)d_in[4];
    const float* Wc   = (const float*)d_in[5];   // [2,128,128]
    const float* bc   = (const float*)d_in[6];   // [2,128]
    const float* W2   = (const float*)d_in[7];
    const float* b2   = (const float*)d_in[8];
    const float* W3   = (const float*)d_in[9];
    const float* b3   = (const float*)d_in[10];
    const float* Wcls = (const float*)d_in[11];
    const float* bcls = (const float*)d_in[12];

    const int* src = ei;
    const int* dst = ei + EE;

    float* out_logits = (float*)d_out;                       // [E, 6]
    float* out_e      = (float*)d_out + (size_t)EE * CC;     // [E, 64]

    const int node_blocks = (NN + 255) / 256;
    const int edge_blocks = (EE + 255) / 256;
    const int cgemm_blocks = (NN + 127) / 128;
    const int fc_blocks    = (NN + 63) / 64;
    const int warp_blocks = (int)(((long long)EE * 32 + 255) / 256);   // warp-per-edge
    const int gath_blocks = (int)(((long long)NN * 32 + 255) / 256);   // warp-per-node

    // ---- CSR build (also produces dinv) ----
    zero_cnt_k<<<node_blocks, 256>>>();
    count_k<<<edge_blocks, 256>>>(dst);
    scanA_k<<<NBLK, SCAN_BLK>>>();
    scanB_k<<<1, 32>>>();
    scanC_k<<<node_blocks, 256>>>();
    fill_k<<<edge_blocks, 256>>>(src, dst);

    // ---- conv layer 1 (reads x) ----
    cgemm_k<0><<<cgemm_blocks, 256>>>(x, W1, NN);
    gather_k<<<gath_blocks, 256>>>(b1);

    // ---- conv layers 2,3 (read g_h) ----
    for (int layer = 0; layer < 2; ++layer) {
        const float* W = Wc + (size_t)layer * DIM * DIM;
        const float* b = bc + (size_t)layer * DIM;
        cgemm_k<1><<<cgemm_blocks, 256>>>(nullptr, W, NN);
        gather_k<<<gath_blocks, 256>>>(b);
    }

    // ---- fc layers ----
    gemm_k<128, 64, 4, 4, 1, 1><<<fc_blocks, dim3(16, 16)>>>(W2, b2, NN);
    gemm_k< 64, 32, 4, 4, 2, 2><<<fc_blocks, dim3( 8, 16)>>>(W3, b3, NN);

    // ---- edge classifier + e ----
    edge_out_k<<<warp_blocks, 256>>>(src, dst, Wcls, bcls, out_logits, out_e);
}

// round 6
// speedup vs baseline: 2.0574x; 1.3535x over previous
#include <cuda_runtime.h>
#include <cuda_bf16.h>
#include <math.h>

// Problem constants (fixed by the dataset)
#define NN 100000
#define EE 1600000
#define FF 128
#define DIM 128
#define DIM2 64
#define DIM4 32
#define CC 6

#define SCAN_BLK 1024
#define NBLK ((NN + SCAN_BLK - 1) / SCAN_BLK)   // 98

// ---- packed f32x2 helpers (sm_103a) ----
#define FMA2(d, a, b) \
    asm("fma.rn.f32x2 %0, %1, %2, %0;" : "+l"(d) : "l"(a), "l"(b))
#define PACK2_DUP(out, f) \
    asm("mov.b64 %0, {%1, %1};" : "=l"(out) : "f"(f))
#define UNPACK2(lo, hi, v) \
    asm("mov.b64 {%0, %1}, %2;" : "=f"(lo), "=f"(hi) : "l"(v))

// ---------------- device scratch (allocation-free rule, 16B aligned) ----------------
__device__ float  g_dinv[NN];
__device__ int    g_cnt [NN];
__device__ int    g_rp  [NN];
__device__ int    g_fill[NN];
__device__ int    g_bsum[NBLK];
__device__ int    g_boff[NBLK];
__device__ int    g_eidx[EE];
__device__ float4 g_hw4 [(size_t)NN * DIM  / 4];
__device__ float4 g_h4  [(size_t)NN * DIM  / 4];
__device__ float4 g_h24 [(size_t)NN * DIM2 / 4];
__device__ float4 g_h34 [(size_t)NN * DIM4 / 4];
__device__ float  g_logA[(size_t)NN * 8];   // 6 used, pad to 8
__device__ float  g_logB[(size_t)NN * 8];

// ---------------- CSR build ----------------
__global__ void zero_cnt_k() {
    int i = blockIdx.x * blockDim.x + threadIdx.x;
    if (i < NN) g_cnt[i] = 0;
}

__global__ void count_k(const int* __restrict__ dst) {
    int e = blockIdx.x * blockDim.x + threadIdx.x;
    if (e < EE) atomicAdd(&g_cnt[dst[e]], 1);
}

// per-block exclusive scan (Hillis-Steele in smem) + block totals
__global__ void scanA_k() {
    __shared__ int sh[SCAN_BLK];
    int t = threadIdx.x, b = blockIdx.x;
    int i = b * SCAN_BLK + t;
    int v = (i < NN) ? g_cnt[i] : 0;
    sh[t] = v;
    __syncthreads();
    for (int off = 1; off < SCAN_BLK; off <<= 1) {
        int add = (t >= off) ? sh[t - off] : 0;
        __syncthreads();
        sh[t] += add;
        __syncthreads();
    }
    if (i < NN) g_rp[i] = sh[t] - v;      // exclusive within block
    if (t == SCAN_BLK - 1) g_bsum[b] = sh[t];
}

// 1-block parallel scan over NBLK (=98) block sums
__global__ void scanB_k() {
    __shared__ int sh[128];
    int t = threadIdx.x;
    int v = (t < NBLK) ? g_bsum[t] : 0;
    sh[t] = v;
    __syncthreads();
    for (int off = 1; off < 128; off <<= 1) {
        int add = (t >= off) ? sh[t - off] : 0;
        __syncthreads();
        sh[t] += add;
        __syncthreads();
    }
    if (t < NBLK) g_boff[t] = sh[t] - v;  // exclusive
}

// finalize row_ptr, init fill cursors, compute dinv from degree
__global__ void scanC_k() {
    int i = blockIdx.x * blockDim.x + threadIdx.x;
    if (i < NN) {
        int rp = g_rp[i] + g_boff[i / SCAN_BLK];
        g_rp[i]   = rp;
        g_fill[i] = rp;
        g_dinv[i] = rsqrtf((float)g_cnt[i] + 1.0f);
    }
}

__global__ void fill_k(const int* __restrict__ src, const int* __restrict__ dst) {
    int e = blockIdx.x * blockDim.x + threadIdx.x;
    if (e < EE) {
        int pos = atomicAdd(&g_fill[dst[e]], 1);
        g_eidx[pos] = src[e];
    }
}

// ---------------- f32x2 conv GEMM: hw[M x 128] = A[M x 128] @ W[128 x 128] ----------------
// BM=128, BN=128, KT=16, 256 threads, 8x8 microtile with packed fma.rn.f32x2
// SRC: 0 = Aparam (x), 1 = g_h
template<int SRC>
__global__ void __launch_bounds__(256, 2) cgemm_k(const float* __restrict__ Aparam,
                                                  const float* __restrict__ W, int M)
{
    __shared__ float As[16][132];    // K-major: As[k][row]
    __shared__ float Ws[16][132];    // K-major: Ws[k][col]

    const float* A = (SRC == 0) ? Aparam : (const float*)g_h4;
    float* O = (float*)g_hw4;

    const int tid = threadIdx.x;
    const int tx = tid & 15;         // col block of 8
    const int ty = tid >> 4;         // row block of 8
    const int row0 = blockIdx.x * 128;

    unsigned long long acc2[8][4];
#pragma unroll
    for (int i = 0; i < 8; ++i)
#pragma unroll
        for (int p = 0; p < 4; ++p) acc2[i][p] = 0ull;

    for (int kt = 0; kt < 128; kt += 16) {
        // A tile: 128 rows x 16 k -> store K-major (scatter 4 scalars)
#pragma unroll
        for (int u = 0; u < 2; ++u) {
            int f = tid + u * 256;
            int r = f >> 2, c = (f & 3) << 2;
            int gr = row0 + r;
            float4 v = make_float4(0.f, 0.f, 0.f, 0.f);
            if (gr < M) v = __ldg((const float4*)(A + (size_t)gr * 128 + kt + c));
            As[c + 0][r] = v.x;
            As[c + 1][r] = v.y;
            As[c + 2][r] = v.z;
            As[c + 3][r] = v.w;
        }
        // W tile: 16 k x 128 cols
#pragma unroll
        for (int u = 0; u < 2; ++u) {
            int f = tid + u * 256;
            int r = f >> 5, c = (f & 31) << 2;
            *(float4*)&Ws[r][c] = __ldg((const float4*)(W + (size_t)(kt + r) * 128 + c));
        }
        __syncthreads();

#pragma unroll
        for (int k = 0; k < 16; ++k) {
            const ulonglong2* wp = (const ulonglong2*)&Ws[k][tx * 8];
            ulonglong2 wa = wp[0];
            ulonglong2 wb = wp[1];
            unsigned long long w2[4] = {wa.x, wa.y, wb.x, wb.y};
            float4 a03 = *(const float4*)&As[k][ty * 8];
            float4 a47 = *(const float4*)&As[k][ty * 8 + 4];
            float a[8] = {a03.x, a03.y, a03.z, a03.w, a47.x, a47.y, a47.z, a47.w};
            unsigned long long a2[8];
#pragma unroll
            for (int i = 0; i < 8; ++i) PACK2_DUP(a2[i], a[i]);
#pragma unroll
            for (int i = 0; i < 8; ++i)
#pragma unroll
                for (int p = 0; p < 4; ++p) FMA2(acc2[i][p], a2[i], w2[p]);
        }
        __syncthreads();
    }

#pragma unroll
    for (int i = 0; i < 8; ++i) {
        int row = row0 + ty * 8 + i;
        if (row >= M) continue;
        float o[8];
#pragma unroll
        for (int p = 0; p < 4; ++p) UNPACK2(o[2 * p], o[2 * p + 1], acc2[i][p]);
        float4* op = (float4*)(O + (size_t)row * 128 + tx * 8);
        op[0] = make_float4(o[0], o[1], o[2], o[3]);
        op[1] = make_float4(o[4], o[5], o[6], o[7]);
    }
}

// ---------------- small fp32 GEMM for fc layers: out = tanh(A@W + b) ----------------
// SRC: 1 = g_h, 2 = g_h2 ; OUT: 1 = g_h2, 2 = g_h3
template<int K, int BN, int TM, int TN, int SRC, int OUT>
__global__ void gemm_k(const float* __restrict__ W, const float* __restrict__ bias, int M)
{
    constexpr int BM = 64;
    constexpr int KT = 32;
    constexpr int NT = (BM / TM) * (BN / TN);
    __shared__ float As[BM][KT + 1];
    __shared__ float Ws[KT][BN + 1];

    const float* A = (SRC == 1) ? (const float*)g_h4 : (const float*)g_h24;
    float* O1 = (OUT == 1) ? (float*)g_h24 : (float*)g_h34;

    const int tx  = threadIdx.x;
    const int ty  = threadIdx.y;
    const int tid = ty * (BN / TN) + tx;
    const int row0 = blockIdx.x * BM;

    float acc[TM][TN];
#pragma unroll
    for (int i = 0; i < TM; ++i)
#pragma unroll
        for (int j = 0; j < TN; ++j) acc[i][j] = 0.f;

    for (int kt = 0; kt < K; kt += KT) {
        for (int i = tid; i < BM * KT; i += NT) {
            int r = i / KT, c = i % KT;
            int gr = row0 + r;
            As[r][c] = (gr < M) ? A[(size_t)gr * K + kt + c] : 0.f;
        }
        for (int i = tid; i < KT * BN; i += NT) {
            int r = i / BN, c = i % BN;
            Ws[r][c] = W[(size_t)(kt + r) * BN + c];
        }
        __syncthreads();

#pragma unroll
        for (int k = 0; k < KT; ++k) {
            float a[TM], w[TN];
#pragma unroll
            for (int i = 0; i < TM; ++i) a[i] = As[ty * TM + i][k];
#pragma unroll
            for (int j = 0; j < TN; ++j) w[j] = Ws[k][tx + j * (BN / TN)];
#pragma unroll
            for (int i = 0; i < TM; ++i)
#pragma unroll
                for (int j = 0; j < TN; ++j) acc[i][j] = fmaf(a[i], w[j], acc[i][j]);
        }
        __syncthreads();
    }

#pragma unroll
    for (int i = 0; i < TM; ++i) {
        int row = row0 + ty * TM + i;
        if (row >= M) continue;
#pragma unroll
        for (int j = 0; j < TN; ++j) {
            int col = tx + j * (BN / TN);
            O1[(size_t)row * BN + col] = tanhf(acc[i][j] + bias[col]);
        }
    }
}

// ---------------- CSR gather + self-loop + bias + tanh ----------------
// warp per dst node, lane holds one float4 (128 features total), 4-deep MLP
__global__ void gather_k(const float* __restrict__ bias)
{
    int d    = (blockIdx.x * blockDim.x + threadIdx.x) >> 5;
    int lane = threadIdx.x & 31;
    if (d >= NN) return;

    int   beg = __ldg(&g_rp[d]);
    int   cnt = __ldg(&g_cnt[d]);
    float di  = __ldg(&g_dinv[d]);

    float4 self = __ldg(&g_hw4[(size_t)d * (DIM / 4) + lane]);
    float  dd   = di * di;
    float4 acc  = make_float4(self.x * dd, self.y * dd, self.z * dd, self.w * dd);

    int j = 0;
    for (; j + 3 < cnt; j += 4) {
        int s0 = __ldg(&g_eidx[beg + j]);
        int s1 = __ldg(&g_eidx[beg + j + 1]);
        int s2 = __ldg(&g_eidx[beg + j + 2]);
        int s3 = __ldg(&g_eidx[beg + j + 3]);
        float c0 = __ldg(&g_dinv[s0]) * di;
        float c1 = __ldg(&g_dinv[s1]) * di;
        float c2 = __ldg(&g_dinv[s2]) * di;
        float c3 = __ldg(&g_dinv[s3]) * di;
        float4 v0 = __ldg(&g_hw4[(size_t)s0 * (DIM / 4) + lane]);
        float4 v1 = __ldg(&g_hw4[(size_t)s1 * (DIM / 4) + lane]);
        float4 v2 = __ldg(&g_hw4[(size_t)s2 * (DIM / 4) + lane]);
        float4 v3 = __ldg(&g_hw4[(size_t)s3 * (DIM / 4) + lane]);
        acc.x = fmaf(c0, v0.x, acc.x); acc.y = fmaf(c0, v0.y, acc.y);
        acc.z = fmaf(c0, v0.z, acc.z); acc.w = fmaf(c0, v0.w, acc.w);
        acc.x = fmaf(c1, v1.x, acc.x); acc.y = fmaf(c1, v1.y, acc.y);
        acc.z = fmaf(c1, v1.z, acc.z); acc.w = fmaf(c1, v1.w, acc.w);
        acc.x = fmaf(c2, v2.x, acc.x); acc.y = fmaf(c2, v2.y, acc.y);
        acc.z = fmaf(c2, v2.z, acc.z); acc.w = fmaf(c2, v2.w, acc.w);
        acc.x = fmaf(c3, v3.x, acc.x); acc.y = fmaf(c3, v3.y, acc.y);
        acc.z = fmaf(c3, v3.z, acc.z); acc.w = fmaf(c3, v3.w, acc.w);
    }
    for (; j < cnt; ++j) {
        int s0 = __ldg(&g_eidx[beg + j]);
        float  c0 = __ldg(&g_dinv[s0]) * di;
        float4 v0 = __ldg(&g_hw4[(size_t)s0 * (DIM / 4) + lane]);
        acc.x = fmaf(c0, v0.x, acc.x); acc.y = fmaf(c0, v0.y, acc.y);
        acc.z = fmaf(c0, v0.z, acc.z); acc.w = fmaf(c0, v0.w, acc.w);
    }

    float4 b4 = __ldg(&((const float4*)bias)[lane]);
    g_h4[(size_t)d * (DIM / 4) + lane] =
        make_float4(tanhf(acc.x + b4.x), tanhf(acc.y + b4.y),
                    tanhf(acc.z + b4.z), tanhf(acc.w + b4.w));
}

// ---------------- per-node partial logits: logA = h3 @ Wcls[0:32], logB = h3 @ Wcls[32:64] ----------------
// thread per node; Wcls staged in smem
__global__ void node_logits_k(const float* __restrict__ Wcls)
{
    __shared__ float Wsh[64 * CC];
    for (int i = threadIdx.x; i < 64 * CC; i += blockDim.x) Wsh[i] = Wcls[i];
    __syncthreads();

    int n = blockIdx.x * blockDim.x + threadIdx.x;
    if (n >= NN) return;

    const float4* h = &g_h34[(size_t)n * 8];
    float la[CC], lb[CC];
#pragma unroll
    for (int c = 0; c < CC; ++c) { la[c] = 0.f; lb[c] = 0.f; }
#pragma unroll
    for (int q = 0; q < 8; ++q) {
        float4 v = __ldg(&h[q]);
        float f[4] = {v.x, v.y, v.z, v.w};
#pragma unroll
        for (int r = 0; r < 4; ++r) {
            int k = q * 4 + r;
#pragma unroll
            for (int c = 0; c < CC; ++c) {
                la[c] = fmaf(f[r], Wsh[k * CC + c], la[c]);
                lb[c] = fmaf(f[r], Wsh[(32 + k) * CC + c], lb[c]);
            }
        }
    }
#pragma unroll
    for (int c = 0; c < CC; ++c) {
        g_logA[(size_t)n * 8 + c] = la[c];
        g_logB[(size_t)n * 8 + c] = lb[c];
    }
}

// ---------------- e output copy: warp handles 2 edges, float4 lanes ----------------
__global__ void edge_e_k(const int* __restrict__ src, const int* __restrict__ dst,
                         float4* __restrict__ e_out4)
{
    int t = blockIdx.x * blockDim.x + threadIdx.x;
    long long epair = (long long)(t >> 5) * 2 + ((t >> 4) & 1);
    if (epair >= EE) return;
    int l = t & 15;            // 0..15: 8 for src half, 8 for dst half
    int e = (int)epair;
    int node = (l < 8) ? __ldg(&src[e]) : __ldg(&dst[e]);
    int q = l & 7;
    float4 v = __ldg(&g_h34[(size_t)node * 8 + q]);
    e_out4[(size_t)e * 16 + l] = v;
}

// ---------------- logits output: thread per edge ----------------
__global__ void edge_logit_k(const int* __restrict__ src, const int* __restrict__ dst,
                             const float* __restrict__ bcls, float* __restrict__ out)
{
    int e = blockIdx.x * blockDim.x + threadIdx.x;
    if (e >= EE) return;
    int s = __ldg(&src[e]);
    int d = __ldg(&dst[e]);
    const float* pa = &g_logA[(size_t)s * 8];
    const float* pb = &g_logB[(size_t)d * 8];
    float* po = out + (size_t)e * CC;
#pragma unroll
    for (int c = 0; c < CC; ++c)
        po[c] = __ldg(&pa[c]) + __ldg(&pb[c]) + __ldg(&bcls[c]);
}

// ---------------- launch ----------------
extern "C" void kernel_launch(void* const* d_in, const int* in_sizes, int n_in,
                              void* d_out, int out_size)
{
    const float* x    = (const float*)d_in[0];
    const int*   ei   = (const int*)d_in[1];     // int32 (JAX x64 disabled)
    // d_in[2] = batch (unused)
    const float* W1   = (const float*)d_in[3];
    const float* b1   = (const float*)d_in[4];
    const float* Wc   = (const float*)d_in[5];   // [2,128,128]
    const float* bc   = (const float*)d_in[6];   // [2,128]
    const float* W2   = (const float*)d_in[7];
    const float* b2   = (const float*)d_in[8];
    const float* W3   = (const float*)d_in[9];
    const float* b3   = (const float*)d_in[10];
    const float* Wcls = (const float*)d_in[11];
    const float* bcls = (const float*)d_in[12];

    const int* src = ei;
    const int* dst = ei + EE;

    float* out_logits = (float*)d_out;                       // [E, 6]
    float* out_e      = (float*)d_out + (size_t)EE * CC;     // [E, 64]

    const int node_blocks = (NN + 255) / 256;
    const int edge_blocks = (EE + 255) / 256;
    const int cgemm_blocks = (NN + 127) / 128;
    const int fc_blocks    = (NN + 63) / 64;
    const int gath_blocks = (int)(((long long)NN * 32 + 255) / 256);    // warp-per-node
    const int ecpy_blocks = (int)(((long long)EE * 16 + 255) / 256);    // 16 threads/edge

    // ---- CSR build (also produces dinv) ----
    zero_cnt_k<<<node_blocks, 256>>>();
    count_k<<<edge_blocks, 256>>>(dst);
    scanA_k<<<NBLK, SCAN_BLK>>>();
    scanB_k<<<1, 128>>>();
    scanC_k<<<node_blocks, 256>>>();
    fill_k<<<edge_blocks, 256>>>(src, dst);

    // ---- conv layer 1 (reads x) ----
    cgemm_k<0><<<cgemm_blocks, 256>>>(x, W1, NN);
    gather_k<<<gath_blocks, 256>>>(b1);

    // ---- conv layers 2,3 (read g_h) ----
    for (int layer = 0; layer < 2; ++layer) {
        const float* W = Wc + (size_t)layer * DIM * DIM;
        const float* b = bc + (size_t)layer * DIM;
        cgemm_k<1><<<cgemm_blocks, 256>>>(nullptr, W, NN);
        gather_k<<<gath_blocks, 256>>>(b);
    }

    // ---- fc layers ----
    gemm_k<128, 64, 4, 4, 1, 1><<<fc_blocks, dim3(16, 16)>>>(W2, b2, NN);
    gemm_k< 64, 32, 4, 4, 2, 2><<<fc_blocks, dim3( 8, 16)>>>(W3, b3, NN);

    // ---- edge outputs ----
    node_logits_k<<<node_blocks, 256>>>(Wcls);
    edge_e_k<<<ecpy_blocks, 256>>>(src, dst, (float4*)out_e);
    edge_logit_k<<<edge_blocks, 256>>>(src, dst, bcls, out_logits);
}

// round 7
// speedup vs baseline: 2.0590x; 1.0008x over previous
#include <cuda_runtime.h>
#include <cuda_bf16.h>
#include <math.h>

// Problem constants (fixed by the dataset)
#define NN 100000
#define EE 1600000
#define FF 128
#define DIM 128
#define DIM2 64
#define DIM4 32
#define CC 6

#define SCAN_BLK 1024
#define NBLK ((NN + SCAN_BLK - 1) / SCAN_BLK)   // 98

// ---- packed f32x2 helpers (sm_103a) ----
#define FMA2(d, a, b) \
    asm("fma.rn.f32x2 %0, %1, %2, %0;" : "+l"(d) : "l"(a), "l"(b))
#define PACK2_DUP(out, f) \
    asm("mov.b64 %0, {%1, %1};" : "=l"(out) : "f"(f))
#define UNPACK2(lo, hi, v) \
    asm("mov.b64 {%0, %1}, %2;" : "=f"(lo), "=f"(hi) : "l"(v))

// ---------------- device scratch (allocation-free rule, 16B aligned) ----------------
__device__ float  g_dinv[NN];
__device__ int    g_cnt [NN];
__device__ int    g_rp  [NN];
__device__ int    g_fill[NN];
__device__ int    g_bsum[NBLK];
__device__ int    g_boff[NBLK];
__device__ int    g_eidx[EE];
__device__ float4 g_hw4 [(size_t)NN * DIM  / 4];
__device__ float4 g_h4  [(size_t)NN * DIM  / 4];
__device__ float4 g_h24 [(size_t)NN * DIM2 / 4];
__device__ float4 g_h34 [(size_t)NN * DIM4 / 4];
__device__ float  g_logA[(size_t)NN * 8];   // 6 used, pad to 8
__device__ float  g_logB[(size_t)NN * 8];

// ---------------- CSR build ----------------
__global__ void zero_cnt_k() {
    int i = blockIdx.x * blockDim.x + threadIdx.x;
    if (i < NN) g_cnt[i] = 0;
}

__global__ void count_k(const int* __restrict__ dst) {
    int e = blockIdx.x * blockDim.x + threadIdx.x;
    if (e < EE) atomicAdd(&g_cnt[dst[e]], 1);
}

// per-block exclusive scan (Hillis-Steele in smem) + block totals
__global__ void scanA_k() {
    __shared__ int sh[SCAN_BLK];
    int t = threadIdx.x, b = blockIdx.x;
    int i = b * SCAN_BLK + t;
    int v = (i < NN) ? g_cnt[i] : 0;
    sh[t] = v;
    __syncthreads();
    for (int off = 1; off < SCAN_BLK; off <<= 1) {
        int add = (t >= off) ? sh[t - off] : 0;
        __syncthreads();
        sh[t] += add;
        __syncthreads();
    }
    if (i < NN) g_rp[i] = sh[t] - v;      // exclusive within block
    if (t == SCAN_BLK - 1) g_bsum[b] = sh[t];
}

// 1-block parallel scan over NBLK (=98) block sums
__global__ void scanB_k() {
    __shared__ int sh[128];
    int t = threadIdx.x;
    int v = (t < NBLK) ? g_bsum[t] : 0;
    sh[t] = v;
    __syncthreads();
    for (int off = 1; off < 128; off <<= 1) {
        int add = (t >= off) ? sh[t - off] : 0;
        __syncthreads();
        sh[t] += add;
        __syncthreads();
    }
    if (t < NBLK) g_boff[t] = sh[t] - v;  // exclusive
}

// finalize row_ptr, init fill cursors, compute dinv from degree
__global__ void scanC_k() {
    int i = blockIdx.x * blockDim.x + threadIdx.x;
    if (i < NN) {
        int rp = g_rp[i] + g_boff[i / SCAN_BLK];
        g_rp[i]   = rp;
        g_fill[i] = rp;
        g_dinv[i] = rsqrtf((float)g_cnt[i] + 1.0f);
    }
}

__global__ void fill_k(const int* __restrict__ src, const int* __restrict__ dst) {
    int e = blockIdx.x * blockDim.x + threadIdx.x;
    if (e < EE) {
        int pos = atomicAdd(&g_fill[dst[e]], 1);
        g_eidx[pos] = src[e];
    }
}

// ---------------- f32x2 conv GEMM: hw[M x 128] = A[M x 128] @ W[128 x 128] ----------------
// BM=128, BN=128, KT=16, 256 threads, 8x8 microtile with packed fma.rn.f32x2
// SRC: 0 = Aparam (x), 1 = g_h
template<int SRC>
__global__ void __launch_bounds__(256, 2) cgemm_k(const float* __restrict__ Aparam,
                                                  const float* __restrict__ W, int M)
{
    __shared__ float As[16][132];    // K-major: As[k][row]
    __shared__ float Ws[16][132];    // K-major: Ws[k][col]

    const float* A = (SRC == 0) ? Aparam : (const float*)g_h4;
    float* O = (float*)g_hw4;

    const int tid = threadIdx.x;
    const int tx = tid & 15;         // col block of 8
    const int ty = tid >> 4;         // row block of 8
    const int row0 = blockIdx.x * 128;

    unsigned long long acc2[8][4];
#pragma unroll
    for (int i = 0; i < 8; ++i)
#pragma unroll
        for (int p = 0; p < 4; ++p) acc2[i][p] = 0ull;

    for (int kt = 0; kt < 128; kt += 16) {
        // A tile: 128 rows x 16 k -> store K-major (scatter 4 scalars)
#pragma unroll
        for (int u = 0; u < 2; ++u) {
            int f = tid + u * 256;
            int r = f >> 2, c = (f & 3) << 2;
            int gr = row0 + r;
            float4 v = make_float4(0.f, 0.f, 0.f, 0.f);
            if (gr < M) v = __ldg((const float4*)(A + (size_t)gr * 128 + kt + c));
            As[c + 0][r] = v.x;
            As[c + 1][r] = v.y;
            As[c + 2][r] = v.z;
            As[c + 3][r] = v.w;
        }
        // W tile: 16 k x 128 cols
#pragma unroll
        for (int u = 0; u < 2; ++u) {
            int f = tid + u * 256;
            int r = f >> 5, c = (f & 31) << 2;
            *(float4*)&Ws[r][c] = __ldg((const float4*)(W + (size_t)(kt + r) * 128 + c));
        }
        __syncthreads();

#pragma unroll
        for (int k = 0; k < 16; ++k) {
            const ulonglong2* wp = (const ulonglong2*)&Ws[k][tx * 8];
            ulonglong2 wa = wp[0];
            ulonglong2 wb = wp[1];
            unsigned long long w2[4] = {wa.x, wa.y, wb.x, wb.y};
            float4 a03 = *(const float4*)&As[k][ty * 8];
            float4 a47 = *(const float4*)&As[k][ty * 8 + 4];
            float a[8] = {a03.x, a03.y, a03.z, a03.w, a47.x, a47.y, a47.z, a47.w};
            unsigned long long a2[8];
#pragma unroll
            for (int i = 0; i < 8; ++i) PACK2_DUP(a2[i], a[i]);
#pragma unroll
            for (int i = 0; i < 8; ++i)
#pragma unroll
                for (int p = 0; p < 4; ++p) FMA2(acc2[i][p], a2[i], w2[p]);
        }
        __syncthreads();
    }

#pragma unroll
    for (int i = 0; i < 8; ++i) {
        int row = row0 + ty * 8 + i;
        if (row >= M) continue;
        float o[8];
#pragma unroll
        for (int p = 0; p < 4; ++p) UNPACK2(o[2 * p], o[2 * p + 1], acc2[i][p]);
        float4* op = (float4*)(O + (size_t)row * 128 + tx * 8);
        op[0] = make_float4(o[0], o[1], o[2], o[3]);
        op[1] = make_float4(o[4], o[5], o[6], o[7]);
    }
}

// ---------------- small fp32 GEMM for fc layers: out = tanh(A@W + b) ----------------
// SRC: 1 = g_h, 2 = g_h2 ; OUT: 1 = g_h2, 2 = g_h3
template<int K, int BN, int TM, int TN, int SRC, int OUT>
__global__ void gemm_k(const float* __restrict__ W, const float* __restrict__ bias, int M)
{
    constexpr int BM = 64;
    constexpr int KT = 32;
    constexpr int NT = (BM / TM) * (BN / TN);
    __shared__ float As[BM][KT + 1];
    __shared__ float Ws[KT][BN + 1];

    const float* A = (SRC == 1) ? (const float*)g_h4 : (const float*)g_h24;
    float* O1 = (OUT == 1) ? (float*)g_h24 : (float*)g_h34;

    const int tx  = threadIdx.x;
    const int ty  = threadIdx.y;
    const int tid = ty * (BN / TN) + tx;
    const int row0 = blockIdx.x * BM;

    float acc[TM][TN];
#pragma unroll
    for (int i = 0; i < TM; ++i)
#pragma unroll
        for (int j = 0; j < TN; ++j) acc[i][j] = 0.f;

    for (int kt = 0; kt < K; kt += KT) {
        for (int i = tid; i < BM * KT; i += NT) {
            int r = i / KT, c = i % KT;
            int gr = row0 + r;
            As[r][c] = (gr < M) ? A[(size_t)gr * K + kt + c] : 0.f;
        }
        for (int i = tid; i < KT * BN; i += NT) {
            int r = i / BN, c = i % BN;
            Ws[r][c] = W[(size_t)(kt + r) * BN + c];
        }
        __syncthreads();

#pragma unroll
        for (int k = 0; k < KT; ++k) {
            float a[TM], w[TN];
#pragma unroll
            for (int i = 0; i < TM; ++i) a[i] = As[ty * TM + i][k];
#pragma unroll
            for (int j = 0; j < TN; ++j) w[j] = Ws[k][tx + j * (BN / TN)];
#pragma unroll
            for (int i = 0; i < TM; ++i)
#pragma unroll
                for (int j = 0; j < TN; ++j) acc[i][j] = fmaf(a[i], w[j], acc[i][j]);
        }
        __syncthreads();
    }

#pragma unroll
    for (int i = 0; i < TM; ++i) {
        int row = row0 + ty * TM + i;
        if (row >= M) continue;
#pragma unroll
        for (int j = 0; j < TN; ++j) {
            int col = tx + j * (BN / TN);
            O1[(size_t)row * BN + col] = tanhf(acc[i][j] + bias[col]);
        }
    }
}

// ---------------- CSR gather + self-loop + bias + tanh ----------------
// warp per dst node, lane holds one float4 (128 features total), 4-deep MLP
__global__ void gather_k(const float* __restrict__ bias)
{
    int d    = (blockIdx.x * blockDim.x + threadIdx.x) >> 5;
    int lane = threadIdx.x & 31;
    if (d >= NN) return;

    int   beg = __ldg(&g_rp[d]);
    int   cnt = __ldg(&g_cnt[d]);
    float di  = __ldg(&g_dinv[d]);

    float4 self = __ldg(&g_hw4[(size_t)d * (DIM / 4) + lane]);
    float  dd   = di * di;
    float4 acc  = make_float4(self.x * dd, self.y * dd, self.z * dd, self.w * dd);

    int j = 0;
    for (; j + 3 < cnt; j += 4) {
        int s0 = __ldg(&g_eidx[beg + j]);
        int s1 = __ldg(&g_eidx[beg + j + 1]);
        int s2 = __ldg(&g_eidx[beg + j + 2]);
        int s3 = __ldg(&g_eidx[beg + j + 3]);
        float c0 = __ldg(&g_dinv[s0]) * di;
        float c1 = __ldg(&g_dinv[s1]) * di;
        float c2 = __ldg(&g_dinv[s2]) * di;
        float c3 = __ldg(&g_dinv[s3]) * di;
        float4 v0 = __ldg(&g_hw4[(size_t)s0 * (DIM / 4) + lane]);
        float4 v1 = __ldg(&g_hw4[(size_t)s1 * (DIM / 4) + lane]);
        float4 v2 = __ldg(&g_hw4[(size_t)s2 * (DIM / 4) + lane]);
        float4 v3 = __ldg(&g_hw4[(size_t)s3 * (DIM / 4) + lane]);
        acc.x = fmaf(c0, v0.x, acc.x); acc.y = fmaf(c0, v0.y, acc.y);
        acc.z = fmaf(c0, v0.z, acc.z); acc.w = fmaf(c0, v0.w, acc.w);
        acc.x = fmaf(c1, v1.x, acc.x); acc.y = fmaf(c1, v1.y, acc.y);
        acc.z = fmaf(c1, v1.z, acc.z); acc.w = fmaf(c1, v1.w, acc.w);
        acc.x = fmaf(c2, v2.x, acc.x); acc.y = fmaf(c2, v2.y, acc.y);
        acc.z = fmaf(c2, v2.z, acc.z); acc.w = fmaf(c2, v2.w, acc.w);
        acc.x = fmaf(c3, v3.x, acc.x); acc.y = fmaf(c3, v3.y, acc.y);
        acc.z = fmaf(c3, v3.z, acc.z); acc.w = fmaf(c3, v3.w, acc.w);
    }
    for (; j < cnt; ++j) {
        int s0 = __ldg(&g_eidx[beg + j]);
        float  c0 = __ldg(&g_dinv[s0]) * di;
        float4 v0 = __ldg(&g_hw4[(size_t)s0 * (DIM / 4) + lane]);
        acc.x = fmaf(c0, v0.x, acc.x); acc.y = fmaf(c0, v0.y, acc.y);
        acc.z = fmaf(c0, v0.z, acc.z); acc.w = fmaf(c0, v0.w, acc.w);
    }

    float4 b4 = __ldg(&((const float4*)bias)[lane]);
    g_h4[(size_t)d * (DIM / 4) + lane] =
        make_float4(tanhf(acc.x + b4.x), tanhf(acc.y + b4.y),
                    tanhf(acc.z + b4.z), tanhf(acc.w + b4.w));
}

// ---------------- per-node partial logits: logA = h3 @ Wcls[0:32], logB = h3 @ Wcls[32:64] ----------------
// thread per node; Wcls staged in smem
__global__ void node_logits_k(const float* __restrict__ Wcls)
{
    __shared__ float Wsh[64 * CC];
    for (int i = threadIdx.x; i < 64 * CC; i += blockDim.x) Wsh[i] = Wcls[i];
    __syncthreads();

    int n = blockIdx.x * blockDim.x + threadIdx.x;
    if (n >= NN) return;

    const float4* h = &g_h34[(size_t)n * 8];
    float la[CC], lb[CC];
#pragma unroll
    for (int c = 0; c < CC; ++c) { la[c] = 0.f; lb[c] = 0.f; }
#pragma unroll
    for (int q = 0; q < 8; ++q) {
        float4 v = __ldg(&h[q]);
        float f[4] = {v.x, v.y, v.z, v.w};
#pragma unroll
        for (int r = 0; r < 4; ++r) {
            int k = q * 4 + r;
#pragma unroll
            for (int c = 0; c < CC; ++c) {
                la[c] = fmaf(f[r], Wsh[k * CC + c], la[c]);
                lb[c] = fmaf(f[r], Wsh[(32 + k) * CC + c], lb[c]);
            }
        }
    }
#pragma unroll
    for (int c = 0; c < CC; ++c) {
        g_logA[(size_t)n * 8 + c] = la[c];
        g_logB[(size_t)n * 8 + c] = lb[c];
    }
}

// ---------------- e output copy: warp handles 2 edges, float4 lanes ----------------
__global__ void edge_e_k(const int* __restrict__ src, const int* __restrict__ dst,
                         float4* __restrict__ e_out4)
{
    int t = blockIdx.x * blockDim.x + threadIdx.x;
    long long epair = (long long)(t >> 5) * 2 + ((t >> 4) & 1);
    if (epair >= EE) return;
    int l = t & 15;            // 0..15: 8 for src half, 8 for dst half
    int e = (int)epair;
    int node = (l < 8) ? __ldg(&src[e]) : __ldg(&dst[e]);
    int q = l & 7;
    float4 v = __ldg(&g_h34[(size_t)node * 8 + q]);
    e_out4[(size_t)e * 16 + l] = v;
}

// ---------------- logits output: thread per edge ----------------
__global__ void edge_logit_k(const int* __restrict__ src, const int* __restrict__ dst,
                             const float* __restrict__ bcls, float* __restrict__ out)
{
    int e = blockIdx.x * blockDim.x + threadIdx.x;
    if (e >= EE) return;
    int s = __ldg(&src[e]);
    int d = __ldg(&dst[e]);
    const float* pa = &g_logA[(size_t)s * 8];
    const float* pb = &g_logB[(size_t)d * 8];
    float* po = out + (size_t)e * CC;
#pragma unroll
    for (int c = 0; c < CC; ++c)
        po[c] = __ldg(&pa[c]) + __ldg(&pb[c]) + __ldg(&bcls[c]);
}

// ---------------- launch ----------------
extern "C" void kernel_launch(void* const* d_in, const int* in_sizes, int n_in,
                              void* d_out, int out_size)
{
    const float* x    = (const float*)d_in[0];
    const int*   ei   = (const int*)d_in[1];     // int32 (JAX x64 disabled)
    // d_in[2] = batch (unused)
    const float* W1   = (const float*)d_in[3];
    const float* b1   = (const float*)d_in[4];
    const float* Wc   = (const float*)d_in[5];   // [2,128,128]
    const float* bc   = (const float*)d_in[6];   // [2,128]
    const float* W2   = (const float*)d_in[7];
    const float* b2   = (const float*)d_in[8];
    const float* W3   = (const float*)d_in[9];
    const float* b3   = (const float*)d_in[10];
    const float* Wcls = (const float*)d_in[11];
    const float* bcls = (const float*)d_in[12];

    const int* src = ei;
    const int* dst = ei + EE;

    float* out_logits = (float*)d_out;                       // [E, 6]
    float* out_e      = (float*)d_out + (size_t)EE * CC;     // [E, 64]

    const int node_blocks = (NN + 255) / 256;
    const int edge_blocks = (EE + 255) / 256;
    const int cgemm_blocks = (NN + 127) / 128;
    const int fc_blocks    = (NN + 63) / 64;
    const int gath_blocks = (int)(((long long)NN * 32 + 255) / 256);    // warp-per-node
    const int ecpy_blocks = (int)(((long long)EE * 16 + 255) / 256);    // 16 threads/edge

    // ---- CSR build (also produces dinv) ----
    zero_cnt_k<<<node_blocks, 256>>>();
    count_k<<<edge_blocks, 256>>>(dst);
    scanA_k<<<NBLK, SCAN_BLK>>>();
    scanB_k<<<1, 128>>>();
    scanC_k<<<node_blocks, 256>>>();
    fill_k<<<edge_blocks, 256>>>(src, dst);

    // ---- conv layer 1 (reads x) ----
    cgemm_k<0><<<cgemm_blocks, 256>>>(x, W1, NN);
    gather_k<<<gath_blocks, 256>>>(b1);

    // ---- conv layers 2,3 (read g_h) ----
    for (int layer = 0; layer < 2; ++layer) {
        const float* W = Wc + (size_t)layer * DIM * DIM;
        const float* b = bc + (size_t)layer * DIM;
        cgemm_k<1><<<cgemm_blocks, 256>>>(nullptr, W, NN);
        gather_k<<<gath_blocks, 256>>>(b);
    }

    // ---- fc layers ----
    gemm_k<128, 64, 4, 4, 1, 1><<<fc_blocks, dim3(16, 16)>>>(W2, b2, NN);
    gemm_k< 64, 32, 4, 4, 2, 2><<<fc_blocks, dim3( 8, 16)>>>(W3, b3, NN);

    // ---- edge outputs ----
    node_logits_k<<<node_blocks, 256>>>(Wcls);
    edge_e_k<<<ecpy_blocks, 256>>>(src, dst, (float4*)out_e);
    edge_logit_k<<<edge_blocks, 256>>>(src, dst, bcls, out_logits);
}